// round 1
// baseline (speedup 1.0000x reference)
#include <cuda_runtime.h>
#include <math.h>

#define BB      32
#define TSLEN   256
#define DD      256
#define FF      256
#define MAXMEL  2048
#define NBINS   256

#define OUT_ELEMS   (BB*MAXMEL*2*DD)          // 33554432
#define LOGDUR_OFF  OUT_ELEMS                  // 33554432
#define PITCH_OFF   (LOGDUR_OFF + BB*TSLEN)    // 33562624
#define MEL_OFF     (PITCH_OFF + BB*MAXMEL)    // 33628160

#define WSZ (3*DD*FF)   // one transposed conv weight: 768*256

// ---------------- scratch (static device globals; no allocation) -------------
__device__ float g_bufX[BB*MAXMEL*DD];   // expanded linguistics (+ pitch emb)
__device__ float g_bufA[BB*MAXMEL*FF];   // conv/LN ping
__device__ float g_bufB[BB*MAXMEL*FF];   // conv/LN pong
__device__ float g_wt[4*WSZ];            // transposed conv weights
__device__ int   g_idx[BB*MAXMEL];       // gather indices
__device__ int   g_mellen[BB];           // per-batch mel length

// ---------------- weight transpose: W[f,c,k] -> Wt[(k*256+c)*256+f] ----------
__global__ void transpose_w(const float* __restrict__ W, float* __restrict__ Wt) {
    int o = blockIdx.x * 256 + threadIdx.x;   // o = r*256 + f, r in [0,768)
    int r = o >> 8;
    int f = o & 255;
    int k = r >> 8;     // r / 256
    int c = r & 255;
    Wt[o] = W[f*768 + c*3 + k];
}

// ---------------- length regulator: cumsum + searchsorted(right) -------------
__global__ void length_reg(const int* __restrict__ dur, int* __restrict__ idxb,
                           int* __restrict__ mellen, float* __restrict__ out_mel) {
    __shared__ int cum[TSLEN];
    int b = blockIdx.x;
    int t = threadIdx.x;
    cum[t] = dur[b*TSLEN + t];
    __syncthreads();
    // Hillis-Steele inclusive scan
    for (int off = 1; off < TSLEN; off <<= 1) {
        int v = (t >= off) ? cum[t - off] : 0;
        __syncthreads();
        cum[t] += v;
        __syncthreads();
    }
    int ml = min(cum[TSLEN-1], MAXMEL);
    if (t == 0) { mellen[b] = ml; out_mel[b] = (float)ml; }
    for (int m = t; m < MAXMEL; m += TSLEN) {
        // count of cum <= m  (searchsorted side='right')
        int lo = 0, hi = TSLEN;
        while (lo < hi) { int mid = (lo + hi) >> 1; if (cum[mid] <= m) lo = mid + 1; else hi = mid; }
        idxb[b*MAXMEL + m] = min(lo, TSLEN - 1);
    }
}

// ---------------- gather expanded x, zero masked frames ----------------------
__global__ void gather_x(const float* __restrict__ ling, const int* __restrict__ idxb,
                         const int* __restrict__ mellen, float* __restrict__ X) {
    int row = blockIdx.x;                 // b*MAXMEL + m
    int b = row >> 11;
    int m = row & (MAXMEL - 1);
    bool masked = (m >= mellen[b]);
    int src = idxb[row];
    const float4* s = (const float4*)(ling + ((size_t)b*TSLEN + src)*DD);
    float4* d = (float4*)(g_bufX + (size_t)row*DD);
    (void)X;
    float4 v = masked ? make_float4(0.f,0.f,0.f,0.f) : s[threadIdx.x];
    d[threadIdx.x] = v;
}

// ---------------- conv-as-GEMM (K=3 SAME) / plain GEMM (K=1) -----------------
// Y[b,t,f] = sum_{k,c} Wt[(k*256+c), f] * X[b, t+k-(KWIN/2), c]   (+bias, relu, mask)
// Tile: BM=64 tokens x BN=64 channels, BK=32, 256 threads, 4x4 microtile.
template<int KWIN, bool RELU, bool MASK>
__global__ void conv_gemm(const float* __restrict__ X, const float* __restrict__ Wt,
                          const float* __restrict__ bias, float* __restrict__ Y,
                          int T, int Cout, const int* __restrict__ mellen) {
    const int Cin = 256;
    __shared__ float As[64][33];   // [m][r], padded
    __shared__ float Bs[32][64];   // [r][n]

    int b  = blockIdx.z;
    int t0 = blockIdx.x * 64;
    int f0 = blockIdx.y * 64;
    int tid = threadIdx.x;
    int tx = tid & 15, ty = tid >> 4;

    const float* Xb = X + (size_t)b * T * Cin;
    int lr  = tid & 31, lm0 = tid >> 5;   // A-load coords
    int ln  = tid & 63, lr0 = tid >> 6;   // B-load coords

    float acc[4][4];
    #pragma unroll
    for (int i = 0; i < 4; i++)
        #pragma unroll
        for (int j = 0; j < 4; j++) acc[i][j] = 0.f;

    const int RED = KWIN * Cin;
    for (int kk = 0; kk < RED; kk += 32) {
        int k     = kk >> 8;      // kk / 256 (BK=32 divides 256, so constant per slice)
        int cbase = kk & 255;
        // load A tile (coalesced over c)
        #pragma unroll
        for (int i = 0; i < 8; i++) {
            int m = lm0 + i*8;
            int t = t0 + m + k - (KWIN >> 1);
            float v = 0.f;
            if (t >= 0 && t < T) v = Xb[(size_t)t*Cin + cbase + lr];
            As[m][lr] = v;
        }
        // load B tile (coalesced over f)
        #pragma unroll
        for (int i = 0; i < 8; i++) {
            int r = lr0 + i*4;
            Bs[r][ln] = Wt[(size_t)(kk + r)*Cout + f0 + ln];
        }
        __syncthreads();
        #pragma unroll
        for (int r = 0; r < 32; r++) {
            float4 bv = *(const float4*)(&Bs[r][tx*4]);
            float av[4];
            #pragma unroll
            for (int i = 0; i < 4; i++) av[i] = As[ty*4 + i][r];
            #pragma unroll
            for (int i = 0; i < 4; i++) {
                acc[i][0] += av[i] * bv.x;
                acc[i][1] += av[i] * bv.y;
                acc[i][2] += av[i] * bv.z;
                acc[i][3] += av[i] * bv.w;
            }
        }
        __syncthreads();
    }

    int ml = MASK ? mellen[b] : 0;
    #pragma unroll
    for (int i = 0; i < 4; i++) {
        int t = t0 + ty*4 + i;
        bool msk = MASK && (t >= ml);
        #pragma unroll
        for (int j = 0; j < 4; j++) {
            int f = f0 + tx*4 + j;
            float v = acc[i][j] + bias[f];
            if (RELU) v = fmaxf(v, 0.f);
            if (msk)  v = 0.f;
            Y[((size_t)b*T + t)*Cout + f] = v;
        }
    }
}

// ---------------- per-token LayerNorm over F=256 (in place) ------------------
__global__ void layernorm(float* __restrict__ H, const float* __restrict__ g,
                          const float* __restrict__ be) {
    int row = blockIdx.x;
    int t = threadIdx.x;
    float x = H[(size_t)row*FF + t];
    float v1 = x, v2 = x*x;
    #pragma unroll
    for (int o = 16; o; o >>= 1) {
        v1 += __shfl_down_sync(0xffffffffu, v1, o);
        v2 += __shfl_down_sync(0xffffffffu, v2, o);
    }
    __shared__ float s1[8], s2[8];
    __shared__ float mean, rstd;
    int w = t >> 5, l = t & 31;
    if (l == 0) { s1[w] = v1; s2[w] = v2; }
    __syncthreads();
    if (t == 0) {
        float a = 0.f, q = 0.f;
        #pragma unroll
        for (int i = 0; i < 8; i++) { a += s1[i]; q += s2[i]; }
        float m = a * (1.f/256.f);
        float var = q * (1.f/256.f) - m*m;
        mean = m;
        rstd = rsqrtf(var + 1e-5f);
    }
    __syncthreads();
    H[(size_t)row*FF + t] = (x - mean) * rstd * g[t] + be[t];
}

// ---------------- duration linear head (src_mask is all-false) ---------------
__global__ void dp_linear(const float* __restrict__ H, const float* __restrict__ lw,
                          const float* __restrict__ lb, float* __restrict__ outp) {
    int row = blockIdx.x;
    int t = threadIdx.x;
    float v = H[(size_t)row*FF + t] * lw[t];
    #pragma unroll
    for (int o = 16; o; o >>= 1) v += __shfl_down_sync(0xffffffffu, v, o);
    __shared__ float s[8];
    if ((t & 31) == 0) s[t >> 5] = v;
    __syncthreads();
    if (t == 0) {
        float a = 0.f;
        #pragma unroll
        for (int i = 0; i < 8; i++) a += s[i];
        outp[row] = a + lb[0];
    }
}

// ---------------- pitch head: dot + mask + bucketize + emb add ---------------
__global__ void pitch_kernel(const float* __restrict__ H, const float* __restrict__ lw,
                             const float* __restrict__ lb, const float* __restrict__ bins,
                             const float* __restrict__ emb, const int* __restrict__ mellen,
                             float* __restrict__ pout) {
    int row = blockIdx.x;
    int b = row >> 11;
    int m = row & (MAXMEL - 1);
    int t = threadIdx.x;
    float v = H[(size_t)row*FF + t] * lw[t];
    #pragma unroll
    for (int o = 16; o; o >>= 1) v += __shfl_down_sync(0xffffffffu, v, o);
    __shared__ float s[8];
    __shared__ int bkt;
    if ((t & 31) == 0) s[t >> 5] = v;
    __syncthreads();
    if (t == 0) {
        float a = 0.f;
        #pragma unroll
        for (int i = 0; i < 8; i++) a += s[i];
        a += lb[0];
        if (m >= mellen[b]) a = 0.f;       // mask BEFORE bucketize (matches ref)
        pout[row] = a;                      // P_CONTROL = 1.0
        // searchsorted(bins, a) side='left' over 255 bins
        int lo = 0, hi = NBINS - 1;
        while (lo < hi) { int mid = (lo + hi) >> 1; if (bins[mid] < a) lo = mid + 1; else hi = mid; }
        bkt = lo;
    }
    __syncthreads();
    g_bufX[(size_t)row*DD + t] += emb[(size_t)bkt*DD + t];
}

// ------------------------------- launch --------------------------------------
extern "C" void kernel_launch(void* const* d_in, const int* in_sizes, int n_in,
                              void* d_out, int out_size) {
    const float* ling   = (const float*)d_in[0];
    const int*   dur    = (const int*)  d_in[1];
    // d_in[2] = src_mask (all false -> ignored)
    const float* dp_w1  = (const float*)d_in[3];
    const float* dp_b1  = (const float*)d_in[4];
    const float* dp_g1  = (const float*)d_in[5];
    const float* dp_be1 = (const float*)d_in[6];
    const float* dp_w2  = (const float*)d_in[7];
    const float* dp_b2  = (const float*)d_in[8];
    const float* dp_g2  = (const float*)d_in[9];
    const float* dp_be2 = (const float*)d_in[10];
    const float* dp_lw  = (const float*)d_in[11];
    const float* dp_lb  = (const float*)d_in[12];
    const float* pp_w1  = (const float*)d_in[13];
    const float* pp_b1  = (const float*)d_in[14];
    const float* pp_g1  = (const float*)d_in[15];
    const float* pp_be1 = (const float*)d_in[16];
    const float* pp_w2  = (const float*)d_in[17];
    const float* pp_b2  = (const float*)d_in[18];
    const float* pp_g2  = (const float*)d_in[19];
    const float* pp_be2 = (const float*)d_in[20];
    const float* pp_lw  = (const float*)d_in[21];
    const float* pp_lb  = (const float*)d_in[22];
    const float* bins   = (const float*)d_in[23];
    const float* emb    = (const float*)d_in[24];
    const float* proj_w = (const float*)d_in[25];
    const float* proj_b = (const float*)d_in[26];

    float* out = (float*)d_out;

    float *bufX, *bufA, *bufB, *wt;
    int *idxb, *mellen;
    cudaGetSymbolAddress((void**)&bufX,   g_bufX);
    cudaGetSymbolAddress((void**)&bufA,   g_bufA);
    cudaGetSymbolAddress((void**)&bufB,   g_bufB);
    cudaGetSymbolAddress((void**)&wt,     g_wt);
    cudaGetSymbolAddress((void**)&idxb,   g_idx);
    cudaGetSymbolAddress((void**)&mellen, g_mellen);

    // 1) transpose conv weights
    transpose_w<<<768, 256>>>(dp_w1, wt + 0*WSZ);
    transpose_w<<<768, 256>>>(dp_w2, wt + 1*WSZ);
    transpose_w<<<768, 256>>>(pp_w1, wt + 2*WSZ);
    transpose_w<<<768, 256>>>(pp_w2, wt + 3*WSZ);

    // 2) length regulator + gather
    length_reg<<<BB, TSLEN>>>(dur, idxb, mellen, out + MEL_OFF);
    gather_x<<<BB*MAXMEL, 64>>>(ling, idxb, mellen, bufX);

    // 3) duration predictor (T = 256)
    {
        dim3 g(TSLEN/64, FF/64, BB);
        conv_gemm<3, true, false><<<g, 256>>>(ling, wt + 0*WSZ, dp_b1, bufA, TSLEN, FF, nullptr);
        layernorm<<<BB*TSLEN, 256>>>(bufA, dp_g1, dp_be1);
        conv_gemm<3, true, false><<<g, 256>>>(bufA, wt + 1*WSZ, dp_b2, bufB, TSLEN, FF, nullptr);
        layernorm<<<BB*TSLEN, 256>>>(bufB, dp_g2, dp_be2);
        dp_linear<<<BB*TSLEN, 256>>>(bufB, dp_lw, dp_lb, out + LOGDUR_OFF);
    }

    // 4) pitch predictor (T = 2048)
    {
        dim3 g(MAXMEL/64, FF/64, BB);
        conv_gemm<3, true, false><<<g, 256>>>(bufX, wt + 2*WSZ, pp_b1, bufA, MAXMEL, FF, nullptr);
        layernorm<<<BB*MAXMEL, 256>>>(bufA, pp_g1, pp_be1);
        conv_gemm<3, true, false><<<g, 256>>>(bufA, wt + 3*WSZ, pp_b2, bufB, MAXMEL, FF, nullptr);
        layernorm<<<BB*MAXMEL, 256>>>(bufB, pp_g2, pp_be2);
        pitch_kernel<<<BB*MAXMEL, 256>>>(bufB, pp_lw, pp_lb, bins, emb, mellen, out + PITCH_OFF);
    }

    // 5) final projection D -> 2D, masked, straight into d_out
    {
        dim3 g(MAXMEL/64, (2*DD)/64, BB);
        conv_gemm<1, false, true><<<g, 256>>>(bufX, proj_w, proj_b, out, MAXMEL, 2*DD, mellen);
    }
}

// round 2
// speedup vs baseline: 1.0988x; 1.0988x over previous
#include <cuda_runtime.h>
#include <math.h>
#include <stdint.h>

typedef unsigned long long ull;

#define BB      32
#define TSLEN   256
#define DD      256
#define FF      256
#define MAXMEL  2048
#define NBINS   256

#define OUT_ELEMS   (BB*MAXMEL*2*DD)
#define LOGDUR_OFF  OUT_ELEMS
#define PITCH_OFF   (LOGDUR_OFF + BB*TSLEN)
#define MEL_OFF     (PITCH_OFF + BB*MAXMEL)

#define CONVW (3*256*256)      // one prepared conv weight (pair-interleaved)
#define SMEMB ((2*128*36 + 2*16*128)*4)   // 53248 bytes dynamic smem

// ---------------- scratch (static device globals; no allocation) -------------
__device__ float g_bufX[BB*MAXMEL*DD];   // expanded linguistics (+ pitch emb)
__device__ float g_bufA[BB*MAXMEL*FF];
__device__ float g_bufB[BB*MAXMEL*FF];
__device__ float g_wt[4*CONVW + 256*512];
__device__ int   g_idx[BB*MAXMEL];
__device__ int   g_mellen[BB];

// ---------------- packed fp32x2 FMA + cp.async helpers -----------------------
__device__ __forceinline__ void fma2(ull& d, ull a, ull b) {
    asm("fma.rn.f32x2 %0, %1, %2, %0;" : "+l"(d) : "l"(a), "l"(b));
}
__device__ __forceinline__ void cp16(void* smem, const void* g, int sz) {
    uint32_t s = (uint32_t)__cvta_generic_to_shared(smem);
    asm volatile("cp.async.ca.shared.global [%0], [%1], 16, %2;" :: "r"(s), "l"(g), "r"(sz));
}

// ---------------- weight prep: pair-interleave over reduction ----------------
// Conv: W[f, c, k] (f<256, c<256, k<3), reduction r = k*256 + c.
// Out[(rph*256 + f)*2 + par] = W value at r = 2*rph + par.
__global__ void prep_w_conv(const float* __restrict__ W, float* __restrict__ O) {
    int o = blockIdx.x * 256 + threadIdx.x;          // < 196608
    int par = o & 1;
    int f   = (o >> 1) & 255;
    int rph = o >> 9;                                 // 0..383
    int k   = rph >> 7;
    int c   = ((rph & 127) << 1) | par;
    O[o] = W[f*768 + c*3 + k];
}
// Proj: W[k, n] (k<256, n<512). Out[(rph*512+n)*2+par] = W[(2rph+par)*512 + n]
__global__ void prep_w_proj(const float* __restrict__ W, float* __restrict__ O) {
    int o = blockIdx.x * 256 + threadIdx.x;          // < 262144
    int par = o & 1;
    int n   = (o >> 1) & 511;
    int rph = o >> 10;                                // 0..127
    O[o] = W[(2*rph + par)*512 + n];
}

// ---------------- length regulator: cumsum + searchsorted(right) -------------
__global__ void length_reg(const int* __restrict__ dur, int* __restrict__ idxb,
                           int* __restrict__ mellen, float* __restrict__ out_mel) {
    __shared__ int cum[TSLEN];
    int b = blockIdx.x;
    int t = threadIdx.x;
    cum[t] = dur[b*TSLEN + t];
    __syncthreads();
    for (int off = 1; off < TSLEN; off <<= 1) {
        int v = (t >= off) ? cum[t - off] : 0;
        __syncthreads();
        cum[t] += v;
        __syncthreads();
    }
    int ml = min(cum[TSLEN-1], MAXMEL);
    if (t == 0) { mellen[b] = ml; out_mel[b] = (float)ml; }
    for (int m = t; m < MAXMEL; m += TSLEN) {
        int lo = 0, hi = TSLEN;
        while (lo < hi) { int mid = (lo + hi) >> 1; if (cum[mid] <= m) lo = mid + 1; else hi = mid; }
        idxb[b*MAXMEL + m] = min(lo, TSLEN - 1);
    }
}

// ---------------- gather expanded x, zero masked frames ----------------------
__global__ void gather_x(const float* __restrict__ ling, const int* __restrict__ idxb,
                         const int* __restrict__ mellen) {
    int row = blockIdx.x;                 // b*MAXMEL + m
    int b = row >> 11;
    int m = row & (MAXMEL - 1);
    bool masked = (m >= mellen[b]);
    int src = idxb[row];
    const float4* s = (const float4*)(ling + ((size_t)b*TSLEN + src)*DD);
    float4* d = (float4*)(g_bufX + (size_t)row*DD);
    float4 v = masked ? make_float4(0.f,0.f,0.f,0.f) : s[threadIdx.x];
    d[threadIdx.x] = v;
}

// ---------------- f32x2 GEMM, conv-as-GEMM (K=3 SAME) / plain (KWIN=1) -------
// Y[row, n] = sum_{k,c} Wp[pairrow, n, par] * X[row + k - KWIN/2, c]  (+bias/relu/mask)
// 128(M) x 64(N) tile, BK=32, 256 threads, 8x4 microtile, acc paired over K.
template<int KWIN, bool RELU, bool MASK, int TSHIFT>
__global__ __launch_bounds__(256, 2)
void gemm_f32x2(const float* __restrict__ X, const float* __restrict__ Wp,
                const float* __restrict__ bias, float* __restrict__ Y,
                int Cout, const int* __restrict__ mellen) {
    constexpr int Tb = 1 << TSHIFT;
    constexpr int NS = KWIN * 256 / 32;
    extern __shared__ float sm[];
    float* As = sm;                    // [2][128][36]  (rows: 32 k + 4 pad)
    float* Bs = sm + 2*128*36;         // [2][16][64*2] (pair-interleaved over k)

    const int tid  = threadIdx.x;
    const int row0 = blockIdx.x * 128;
    const int n0   = blockIdx.y * 64;
    const int tloc0    = row0 & (Tb - 1);
    const int bRowBase = row0 - tloc0;      // b * Tb

    // loader indices
    const int am = tid >> 1;            // A row 0..127
    const int ac = (tid & 1) * 16;      // A col chunk 0 / 16
    const int brp = tid >> 4;           // B pair-row 0..15
    const int bv  = tid & 15;           // B float4 idx

    // compute indices
    const int ty = tid >> 4;            // m-base = ty*8
    const int tx = tid & 15;            // n = tx + 16*j

    ull acc[8][4];
    #pragma unroll
    for (int i = 0; i < 8; i++)
        #pragma unroll
        for (int j = 0; j < 4; j++) acc[i][j] = 0ULL;

    auto issue_stage = [&](int s, int buf) {
        int kk    = s * 32;
        int ktap  = kk >> 8;
        int cbase = kk & 255;
        // A: 4 x 16B per thread
        int src = tloc0 + am + ktap - (KWIN >> 1);
        bool valid = (KWIN == 1) ? true : (src >= 0 && src < Tb);
        int srcc = valid ? src : 0;
        const float* gA = X + ((size_t)(bRowBase + srcc))*256 + cbase + ac;
        float* sA = As + buf*(128*36) + am*36 + ac;
        int sz = valid ? 16 : 0;
        #pragma unroll
        for (int u = 0; u < 4; u++) cp16(sA + 4*u, gA + 4*u, sz);
        // B: 2 x 16B per thread
        int rph = (kk >> 1) + brp;
        const float* gB = Wp + ((size_t)rph*Cout + n0)*2 + bv*4;
        float* sB = Bs + buf*(16*128) + brp*128 + bv*4;
        cp16(sB,      gB,      16);
        cp16(sB + 64, gB + 64, 16);
        asm volatile("cp.async.commit_group;");
    };

    auto compute_stage = [&](int buf) {
        const float* Ab = As + buf*(128*36);
        const float* Bb = Bs + buf*(16*128);
        #pragma unroll
        for (int rp2 = 0; rp2 < 8; rp2++) {
            ull b0[4], b1[4];
            #pragma unroll
            for (int j = 0; j < 4; j++) {
                b0[j] = *(const ull*)(Bb + (rp2*2+0)*128 + (tx + 16*j)*2);
                b1[j] = *(const ull*)(Bb + (rp2*2+1)*128 + (tx + 16*j)*2);
            }
            #pragma unroll
            for (int i = 0; i < 8; i++) {
                ulonglong2 a = *(const ulonglong2*)(Ab + (ty*8 + i)*36 + rp2*4);
                #pragma unroll
                for (int j = 0; j < 4; j++) {
                    fma2(acc[i][j], a.x, b0[j]);
                    fma2(acc[i][j], a.y, b1[j]);
                }
            }
        }
    };

    issue_stage(0, 0);
    #pragma unroll 1
    for (int s = 0; s < NS; s++) {
        if (s + 1 < NS) {
            issue_stage(s + 1, (s + 1) & 1);
            asm volatile("cp.async.wait_group 1;");
        } else {
            asm volatile("cp.async.wait_group 0;");
        }
        __syncthreads();
        compute_stage(s & 1);
        __syncthreads();
    }

    const int mlv = MASK ? mellen[bRowBase >> TSHIFT] : 0;
    #pragma unroll
    for (int i = 0; i < 8; i++) {
        int row = row0 + ty*8 + i;
        bool msk = MASK && ((row & (Tb - 1)) >= mlv);
        #pragma unroll
        for (int j = 0; j < 4; j++) {
            int n = n0 + tx + 16*j;
            float2 p = *reinterpret_cast<float2*>(&acc[i][j]);
            float v = p.x + p.y + bias[n];
            if (RELU) v = fmaxf(v, 0.f);
            if (msk)  v = 0.f;
            Y[(size_t)row*Cout + n] = v;
        }
    }
}

// ---------------- per-token LayerNorm over F=256 (in place) ------------------
__global__ void layernorm(float* __restrict__ H, const float* __restrict__ g,
                          const float* __restrict__ be) {
    int row = blockIdx.x;
    int t = threadIdx.x;
    float x = H[(size_t)row*FF + t];
    float v1 = x, v2 = x*x;
    #pragma unroll
    for (int o = 16; o; o >>= 1) {
        v1 += __shfl_down_sync(0xffffffffu, v1, o);
        v2 += __shfl_down_sync(0xffffffffu, v2, o);
    }
    __shared__ float s1[8], s2[8];
    __shared__ float mean, rstd;
    int w = t >> 5, l = t & 31;
    if (l == 0) { s1[w] = v1; s2[w] = v2; }
    __syncthreads();
    if (t == 0) {
        float a = 0.f, q = 0.f;
        #pragma unroll
        for (int i = 0; i < 8; i++) { a += s1[i]; q += s2[i]; }
        float m = a * (1.f/256.f);
        float var = q * (1.f/256.f) - m*m;
        mean = m;
        rstd = rsqrtf(var + 1e-5f);
    }
    __syncthreads();
    H[(size_t)row*FF + t] = (x - mean) * rstd * g[t] + be[t];
}

// ---------------- duration linear head (src_mask is all-false) ---------------
__global__ void dp_linear(const float* __restrict__ H, const float* __restrict__ lw,
                          const float* __restrict__ lb, float* __restrict__ outp) {
    int row = blockIdx.x;
    int t = threadIdx.x;
    float v = H[(size_t)row*FF + t] * lw[t];
    #pragma unroll
    for (int o = 16; o; o >>= 1) v += __shfl_down_sync(0xffffffffu, v, o);
    __shared__ float s[8];
    if ((t & 31) == 0) s[t >> 5] = v;
    __syncthreads();
    if (t == 0) {
        float a = 0.f;
        #pragma unroll
        for (int i = 0; i < 8; i++) a += s[i];
        outp[row] = a + lb[0];
    }
}

// ---------------- pitch head: dot + mask + bucketize + emb add ---------------
__global__ void pitch_kernel(const float* __restrict__ H, const float* __restrict__ lw,
                             const float* __restrict__ lb, const float* __restrict__ bins,
                             const float* __restrict__ emb, const int* __restrict__ mellen,
                             float* __restrict__ pout) {
    int row = blockIdx.x;
    int b = row >> 11;
    int m = row & (MAXMEL - 1);
    int t = threadIdx.x;
    float v = H[(size_t)row*FF + t] * lw[t];
    #pragma unroll
    for (int o = 16; o; o >>= 1) v += __shfl_down_sync(0xffffffffu, v, o);
    __shared__ float s[8];
    __shared__ int bkt;
    if ((t & 31) == 0) s[t >> 5] = v;
    __syncthreads();
    if (t == 0) {
        float a = 0.f;
        #pragma unroll
        for (int i = 0; i < 8; i++) a += s[i];
        a += lb[0];
        if (m >= mellen[b]) a = 0.f;       // mask BEFORE bucketize (matches ref)
        pout[row] = a;                      // P_CONTROL = 1.0
        int lo = 0, hi = NBINS - 1;
        while (lo < hi) { int mid = (lo + hi) >> 1; if (bins[mid] < a) lo = mid + 1; else hi = mid; }
        bkt = lo;
    }
    __syncthreads();
    g_bufX[(size_t)row*DD + t] += emb[(size_t)bkt*DD + t];
}

// ------------------------------- launch --------------------------------------
extern "C" void kernel_launch(void* const* d_in, const int* in_sizes, int n_in,
                              void* d_out, int out_size) {
    const float* ling   = (const float*)d_in[0];
    const int*   dur    = (const int*)  d_in[1];
    const float* dp_w1  = (const float*)d_in[3];
    const float* dp_b1  = (const float*)d_in[4];
    const float* dp_g1  = (const float*)d_in[5];
    const float* dp_be1 = (const float*)d_in[6];
    const float* dp_w2  = (const float*)d_in[7];
    const float* dp_b2  = (const float*)d_in[8];
    const float* dp_g2  = (const float*)d_in[9];
    const float* dp_be2 = (const float*)d_in[10];
    const float* dp_lw  = (const float*)d_in[11];
    const float* dp_lb  = (const float*)d_in[12];
    const float* pp_w1  = (const float*)d_in[13];
    const float* pp_b1  = (const float*)d_in[14];
    const float* pp_g1  = (const float*)d_in[15];
    const float* pp_be1 = (const float*)d_in[16];
    const float* pp_w2  = (const float*)d_in[17];
    const float* pp_b2  = (const float*)d_in[18];
    const float* pp_g2  = (const float*)d_in[19];
    const float* pp_be2 = (const float*)d_in[20];
    const float* pp_lw  = (const float*)d_in[21];
    const float* pp_lb  = (const float*)d_in[22];
    const float* bins   = (const float*)d_in[23];
    const float* emb    = (const float*)d_in[24];
    const float* proj_w = (const float*)d_in[25];
    const float* proj_b = (const float*)d_in[26];

    float* out = (float*)d_out;

    float *bufX, *bufA, *bufB, *wt;
    int *idxb, *mellen;
    cudaGetSymbolAddress((void**)&bufX,   g_bufX);
    cudaGetSymbolAddress((void**)&bufA,   g_bufA);
    cudaGetSymbolAddress((void**)&bufB,   g_bufB);
    cudaGetSymbolAddress((void**)&wt,     g_wt);
    cudaGetSymbolAddress((void**)&idxb,   g_idx);
    cudaGetSymbolAddress((void**)&mellen, g_mellen);

    cudaFuncSetAttribute(gemm_f32x2<3,true,false,8>,  cudaFuncAttributeMaxDynamicSharedMemorySize, SMEMB);
    cudaFuncSetAttribute(gemm_f32x2<3,true,false,11>, cudaFuncAttributeMaxDynamicSharedMemorySize, SMEMB);
    cudaFuncSetAttribute(gemm_f32x2<1,false,true,11>, cudaFuncAttributeMaxDynamicSharedMemorySize, SMEMB);

    // 1) weight prep (pair-interleaved layouts)
    prep_w_conv<<<768, 256>>>(dp_w1, wt + 0*CONVW);
    prep_w_conv<<<768, 256>>>(dp_w2, wt + 1*CONVW);
    prep_w_conv<<<768, 256>>>(pp_w1, wt + 2*CONVW);
    prep_w_conv<<<768, 256>>>(pp_w2, wt + 3*CONVW);
    prep_w_proj<<<512, 256>>>(proj_w, wt + 4*CONVW);

    // 2) length regulator + gather
    length_reg<<<BB, TSLEN>>>(dur, idxb, mellen, out + MEL_OFF);
    gather_x<<<BB*MAXMEL, 64>>>(ling, idxb, mellen);

    // 3) duration predictor (rows = 8192, Tb = 256)
    {
        dim3 g(8192/128, 256/64);
        gemm_f32x2<3,true,false,8><<<g, 256, SMEMB>>>(ling, wt + 0*CONVW, dp_b1, bufA, 256, nullptr);
        layernorm<<<BB*TSLEN, 256>>>(bufA, dp_g1, dp_be1);
        gemm_f32x2<3,true,false,8><<<g, 256, SMEMB>>>(bufA, wt + 1*CONVW, dp_b2, bufB, 256, nullptr);
        layernorm<<<BB*TSLEN, 256>>>(bufB, dp_g2, dp_be2);
        dp_linear<<<BB*TSLEN, 256>>>(bufB, dp_lw, dp_lb, out + LOGDUR_OFF);
    }

    // 4) pitch predictor (rows = 65536, Tb = 2048)
    {
        dim3 g(65536/128, 256/64);
        gemm_f32x2<3,true,false,11><<<g, 256, SMEMB>>>(bufX, wt + 2*CONVW, pp_b1, bufA, 256, nullptr);
        layernorm<<<BB*MAXMEL, 256>>>(bufA, pp_g1, pp_be1);
        gemm_f32x2<3,true,false,11><<<g, 256, SMEMB>>>(bufA, wt + 3*CONVW, pp_b2, bufB, 256, nullptr);
        layernorm<<<BB*MAXMEL, 256>>>(bufB, pp_g2, pp_be2);
        pitch_kernel<<<BB*MAXMEL, 256>>>(bufB, pp_lw, pp_lb, bins, emb, mellen, out + PITCH_OFF);
    }

    // 5) final projection D -> 2D, masked, straight into d_out
    {
        dim3 g(65536/128, 512/64);
        gemm_f32x2<1,false,true,11><<<g, 256, SMEMB>>>(bufX, wt + 4*CONVW, proj_b, out, 512, mellen);
    }
}

// round 4
// speedup vs baseline: 2.3836x; 2.1692x over previous
#include <cuda_runtime.h>
#include <cuda_bf16.h>
#include <math.h>
#include <stdint.h>

#define BB      32
#define TSLEN   256
#define DD      256
#define FF      256
#define MAXMEL  2048
#define NBINS   256

#define OUT_ELEMS   (BB*MAXMEL*2*DD)
#define LOGDUR_OFF  OUT_ELEMS
#define PITCH_OFF   (LOGDUR_OFF + BB*TSLEN)
#define MEL_OFF     (PITCH_OFF + BB*MAXMEL)

#define WCONV (256*768)
#define WPROJ (512*256)

typedef __nv_bfloat16 bf16;

// ---------------- scratch (static device globals; no allocation) -------------
__device__ float g_bufX[BB*MAXMEL*DD];          // gathered fp32 (for emb add)
__device__ float g_bufA[BB*MAXMEL*FF];          // GEMM out ping
__device__ float g_bufB[BB*MAXMEL*FF];          // GEMM out pong
__device__ bf16  g_xh[BB*MAXMEL*DD];            // activation hi
__device__ bf16  g_xl[BB*MAXMEL*DD];            // activation lo
__device__ bf16  g_wh[4*WCONV + WPROJ];         // weights hi
__device__ bf16  g_wl[4*WCONV + WPROJ];         // weights lo
__device__ int   g_idx[BB*MAXMEL];
__device__ int   g_mellen[BB];

// ---------------- helpers -----------------------------------------------------
__device__ __forceinline__ void cpa16(uint32_t d, const void* s, int sz) {
    asm volatile("cp.async.ca.shared.global [%0], [%1], 16, %2;" :: "r"(d), "l"(s), "r"(sz));
}
__device__ __forceinline__ void ldm4(uint32_t* r, uint32_t a) {
    asm volatile("ldmatrix.sync.aligned.m8n8.x4.shared.b16 {%0,%1,%2,%3}, [%4];"
        : "=r"(r[0]), "=r"(r[1]), "=r"(r[2]), "=r"(r[3]) : "r"(a));
}
__device__ __forceinline__ void mma16816(float* c, const uint32_t* a, uint32_t b0, uint32_t b1) {
    asm volatile(
        "mma.sync.aligned.m16n8k16.row.col.f32.bf16.bf16.f32 "
        "{%0,%1,%2,%3}, {%4,%5,%6,%7}, {%8,%9}, {%0,%1,%2,%3};"
        : "+f"(c[0]), "+f"(c[1]), "+f"(c[2]), "+f"(c[3])
        : "r"(a[0]), "r"(a[1]), "r"(a[2]), "r"(a[3]), "r"(b0), "r"(b1));
}
__device__ __forceinline__ void split1(float x, bf16& h, bf16& l) {
    h = __float2bfloat16_rn(x);
    l = __float2bfloat16_rn(x - __bfloat162float(h));
}

// SMEM layout: 8 tiles of 128 x 40 bf16 (10240 B each): Ahi[2] Alo[2] Bhi[2] Blo[2]
#define TILEB 10240
#define SOFF_AHI(b) ((b)*TILEB)
#define SOFF_ALO(b) (2*TILEB + (b)*TILEB)
#define SOFF_BHI(b) (4*TILEB + (b)*TILEB)
#define SOFF_BLO(b) (6*TILEB + (b)*TILEB)
#define SM_TOTAL (8*TILEB)

// ---------------- weight prep: fp32 -> bf16 hi/lo, transposed ---------------
// conv: W[f,c,tap] -> row-major [256][768], col r = tap*256 + c
__global__ void prep_w_conv_bf(const float* __restrict__ W,
                               bf16* __restrict__ H, bf16* __restrict__ L) {
    int o = blockIdx.x * 256 + threadIdx.x;      // < 196608
    int f = o / 768;
    int r = o - f * 768;
    int tap = r >> 8;
    int c = r & 255;
    float w = W[f*768 + c*3 + tap];
    bf16 h, l; split1(w, h, l);
    H[o] = h; L[o] = l;
}
// proj: W[k,n] (256x512) -> row-major [512][256]
__global__ void prep_w_proj_bf(const float* __restrict__ W,
                               bf16* __restrict__ H, bf16* __restrict__ L) {
    int o = blockIdx.x * 256 + threadIdx.x;      // < 131072
    int n = o >> 8;
    int k = o & 255;
    float w = W[k*512 + n];
    bf16 h, l; split1(w, h, l);
    H[o] = h; L[o] = l;
}

// ---------------- split fp32 activations -> bf16 hi/lo -----------------------
__global__ void split_f32(const float* __restrict__ in, bf16* __restrict__ hi,
                          bf16* __restrict__ lo) {
    int i = blockIdx.x * 256 + threadIdx.x;     // index of float4
    float4 v = ((const float4*)in)[i];
    bf16 h0,h1,h2,h3, l0,l1,l2,l3;
    split1(v.x,h0,l0); split1(v.y,h1,l1); split1(v.z,h2,l2); split1(v.w,h3,l3);
    ushort4 hv = make_ushort4(__bfloat16_as_ushort(h0), __bfloat16_as_ushort(h1),
                              __bfloat16_as_ushort(h2), __bfloat16_as_ushort(h3));
    ushort4 lv = make_ushort4(__bfloat16_as_ushort(l0), __bfloat16_as_ushort(l1),
                              __bfloat16_as_ushort(l2), __bfloat16_as_ushort(l3));
    ((ushort4*)hi)[i] = hv;
    ((ushort4*)lo)[i] = lv;
}

// ---------------- length regulator -------------------------------------------
__global__ void length_reg(const int* __restrict__ dur, int* __restrict__ idxb,
                           int* __restrict__ mellen, float* __restrict__ out_mel) {
    __shared__ int cum[TSLEN];
    int b = blockIdx.x;
    int t = threadIdx.x;
    cum[t] = dur[b*TSLEN + t];
    __syncthreads();
    for (int off = 1; off < TSLEN; off <<= 1) {
        int v = (t >= off) ? cum[t - off] : 0;
        __syncthreads();
        cum[t] += v;
        __syncthreads();
    }
    int ml = min(cum[TSLEN-1], MAXMEL);
    if (t == 0) { mellen[b] = ml; out_mel[b] = (float)ml; }
    for (int m = t; m < MAXMEL; m += TSLEN) {
        int lo = 0, hi = TSLEN;
        while (lo < hi) { int mid = (lo + hi) >> 1; if (cum[mid] <= m) lo = mid + 1; else hi = mid; }
        idxb[b*MAXMEL + m] = min(lo, TSLEN - 1);
    }
}

// ---------------- gather expanded x + fused hi/lo split ----------------------
__global__ void gather_x(const float* __restrict__ ling, const int* __restrict__ idxb,
                         const int* __restrict__ mellen) {
    int row = blockIdx.x;
    int b = row >> 11;
    int m = row & (MAXMEL - 1);
    bool masked = (m >= mellen[b]);
    int src = idxb[row];
    const float4* s = (const float4*)(ling + ((size_t)b*TSLEN + src)*DD);
    float4 v = masked ? make_float4(0.f,0.f,0.f,0.f) : s[threadIdx.x];
    ((float4*)(g_bufX + (size_t)row*DD))[threadIdx.x] = v;
    bf16 h0,h1,h2,h3, l0,l1,l2,l3;
    split1(v.x,h0,l0); split1(v.y,h1,l1); split1(v.z,h2,l2); split1(v.w,h3,l3);
    ((ushort4*)(g_xh + (size_t)row*DD))[threadIdx.x] =
        make_ushort4(__bfloat16_as_ushort(h0), __bfloat16_as_ushort(h1),
                     __bfloat16_as_ushort(h2), __bfloat16_as_ushort(h3));
    ((ushort4*)(g_xl + (size_t)row*DD))[threadIdx.x] =
        make_ushort4(__bfloat16_as_ushort(l0), __bfloat16_as_ushort(l1),
                     __bfloat16_as_ushort(l2), __bfloat16_as_ushort(l3));
}

// ---------------- HMMA GEMM: Y[rows, Cout] = X * W^T (+bias, relu/mask) ------
// A: pre-split bf16 hi/lo [rows][256] (conv taps give K = KWIN*256)
// B: weights bf16 hi/lo row-major [Cout][K]
// 3-term: AhBh + AlBh + AhBl into fp32 accumulators.
template<int KWIN, bool RELU, bool MASK, int TSHIFT>
__global__ __launch_bounds__(256, 2)
void gemm_mma(const bf16* __restrict__ Ahi, const bf16* __restrict__ Alo,
              const bf16* __restrict__ Whi, const bf16* __restrict__ Wlo,
              const float* __restrict__ bias, float* __restrict__ Y, int Cout,
              const int* __restrict__ mellen) {
    constexpr int Tb = 1 << TSHIFT;
    constexpr int NS = KWIN * 8;            // K stages of 32
    constexpr int K  = KWIN * 256;
    extern __shared__ char smc[];
    const uint32_t sb = (uint32_t)__cvta_generic_to_shared(smc);

    const int tid = threadIdx.x;
    const int wid = tid >> 5, lid = tid & 31;
    const int wm = wid >> 1, wn = wid & 1;       // 4 x 2 warp grid
    const int row0 = blockIdx.x * 128;
    const int n0   = blockIdx.y * 128;
    const int tloc0 = row0 & (Tb - 1);
    const int gseg  = row0 - tloc0;
    const int bIdx  = row0 >> TSHIFT;

    // ldmatrix lane offsets (bytes within tile)
    const uint32_t aoff = (uint32_t)(wm*2560 + ((lid & 15)*40 + ((lid & 16) ? 8 : 0))*2);
    const uint32_t boff = (uint32_t)(wn*5120 + (((lid & 7) + ((lid & 16) ? 8 : 0))*40
                                               + ((lid & 8) ? 8 : 0))*2);

    // loader coords: 2 chunks per thread per tile
    const int r0c = tid >> 2,          kc0 = tid & 3;
    const int r1c = (tid + 256) >> 2,  kc1 = (tid + 256) & 3;

    float acc[2][8][4];
    #pragma unroll
    for (int i = 0; i < 2; i++)
        #pragma unroll
        for (int j = 0; j < 8; j++)
            #pragma unroll
            for (int e = 0; e < 4; e++) acc[i][j][e] = 0.f;

    auto load_stage = [&](int s, int buf) {
        const int tap = (KWIN == 3) ? (s >> 3) : 0;
        const int cb  = (s & 7) * 32;
        // A rows (with conv halo, zero-fill OOB)
        #pragma unroll
        for (int h = 0; h < 2; h++) {
            const int row = h ? r1c : r0c;
            const int kc  = h ? kc1 : kc0;
            const int src = tloc0 + row + tap - (KWIN >> 1);
            const bool valid = (KWIN == 1) || (src >= 0 && src < Tb);
            const size_t go = (size_t)(gseg + (valid ? src : 0))*256 + cb + kc*8;
            const uint32_t d = (uint32_t)((row*40 + kc*8)*2);
            cpa16(sb + SOFF_AHI(buf) + d, Ahi + go, valid ? 16 : 0);
            cpa16(sb + SOFF_ALO(buf) + d, Alo + go, valid ? 16 : 0);
        }
        // B rows
        #pragma unroll
        for (int h = 0; h < 2; h++) {
            const int row = h ? r1c : r0c;
            const int kc  = h ? kc1 : kc0;
            const size_t go = (size_t)(n0 + row)*K + s*32 + kc*8;
            const uint32_t d = (uint32_t)((row*40 + kc*8)*2);
            cpa16(sb + SOFF_BHI(buf) + d, Whi + go, 16);
            cpa16(sb + SOFF_BLO(buf) + d, Wlo + go, 16);
        }
        asm volatile("cp.async.commit_group;");
    };

    auto compute_stage = [&](int buf) {
        const uint32_t sAh = sb + SOFF_AHI(buf) + aoff;
        const uint32_t sAl = sb + SOFF_ALO(buf) + aoff;
        const uint32_t sBh = sb + SOFF_BHI(buf) + boff;
        const uint32_t sBl = sb + SOFF_BLO(buf) + boff;
        #pragma unroll
        for (int q = 0; q < 2; q++) {
            uint32_t ah[2][4], bh[4][4];
            ldm4(ah[0], sAh + q*32);
            ldm4(ah[1], sAh + 1280 + q*32);
            #pragma unroll
            for (int p = 0; p < 4; p++) ldm4(bh[p], sBh + p*1280 + q*32);
            #pragma unroll
            for (int mt = 0; mt < 2; mt++)
                #pragma unroll
                for (int p = 0; p < 4; p++) {
                    mma16816(acc[mt][2*p],   ah[mt], bh[p][0], bh[p][1]);
                    mma16816(acc[mt][2*p+1], ah[mt], bh[p][2], bh[p][3]);
                }
            uint32_t al[2][4];
            ldm4(al[0], sAl + q*32);
            ldm4(al[1], sAl + 1280 + q*32);
            #pragma unroll
            for (int mt = 0; mt < 2; mt++)
                #pragma unroll
                for (int p = 0; p < 4; p++) {
                    mma16816(acc[mt][2*p],   al[mt], bh[p][0], bh[p][1]);
                    mma16816(acc[mt][2*p+1], al[mt], bh[p][2], bh[p][3]);
                }
            uint32_t bl[4][4];
            #pragma unroll
            for (int p = 0; p < 4; p++) ldm4(bl[p], sBl + p*1280 + q*32);
            #pragma unroll
            for (int mt = 0; mt < 2; mt++)
                #pragma unroll
                for (int p = 0; p < 4; p++) {
                    mma16816(acc[mt][2*p],   ah[mt], bl[p][0], bl[p][1]);
                    mma16816(acc[mt][2*p+1], ah[mt], bl[p][2], bl[p][3]);
                }
        }
    };

    load_stage(0, 0);
    #pragma unroll 1
    for (int s = 0; s < NS; s++) {
        if (s + 1 < NS) {
            load_stage(s + 1, (s + 1) & 1);
            asm volatile("cp.async.wait_group 1;");
        } else {
            asm volatile("cp.async.wait_group 0;");
        }
        __syncthreads();
        compute_stage(s & 1);
        __syncthreads();
    }

    // epilogue
    const int mrow = row0 + wm*32;
    const int ncol = n0 + wn*64;
    const int ml = MASK ? mellen[bIdx] : 0;
    #pragma unroll
    for (int mt = 0; mt < 2; mt++) {
        const int r = mrow + mt*16 + (lid >> 2);
        const bool m0 = MASK && ((r     & (Tb-1)) >= ml);
        const bool m1 = MASK && (((r+8) & (Tb-1)) >= ml);
        #pragma unroll
        for (int nt = 0; nt < 8; nt++) {
            const int c = ncol + nt*8 + (lid & 3)*2;
            const float bb0 = bias[c], bb1 = bias[c+1];
            float v0 = acc[mt][nt][0] + bb0, v1 = acc[mt][nt][1] + bb1;
            float v2 = acc[mt][nt][2] + bb0, v3 = acc[mt][nt][3] + bb1;
            if (RELU) { v0 = fmaxf(v0,0.f); v1 = fmaxf(v1,0.f); v2 = fmaxf(v2,0.f); v3 = fmaxf(v3,0.f); }
            if (m0) { v0 = 0.f; v1 = 0.f; }
            if (m1) { v2 = 0.f; v3 = 0.f; }
            *(float2*)(Y + (size_t)r*Cout + c)     = make_float2(v0, v1);
            *(float2*)(Y + (size_t)(r+8)*Cout + c) = make_float2(v2, v3);
        }
    }
}

// ---------------- LayerNorm variants ------------------------------------------
template<bool OUT_SPLIT>
__global__ void layernorm_k(float* __restrict__ H, const float* __restrict__ g,
                            const float* __restrict__ be,
                            bf16* __restrict__ hi, bf16* __restrict__ lo) {
    int row = blockIdx.x;
    int t = threadIdx.x;
    float x = H[(size_t)row*FF + t];
    float v1 = x, v2 = x*x;
    #pragma unroll
    for (int o = 16; o; o >>= 1) {
        v1 += __shfl_down_sync(0xffffffffu, v1, o);
        v2 += __shfl_down_sync(0xffffffffu, v2, o);
    }
    __shared__ float s1[8], s2[8];
    __shared__ float mean, rstd;
    int w = t >> 5, l = t & 31;
    if (l == 0) { s1[w] = v1; s2[w] = v2; }
    __syncthreads();
    if (t == 0) {
        float a = 0.f, q = 0.f;
        #pragma unroll
        for (int i = 0; i < 8; i++) { a += s1[i]; q += s2[i]; }
        float m = a * (1.f/256.f);
        float var = q * (1.f/256.f) - m*m;
        mean = m;
        rstd = rsqrtf(var + 1e-5f);
    }
    __syncthreads();
    float y = (x - mean) * rstd * g[t] + be[t];
    if (OUT_SPLIT) {
        bf16 h, ll; split1(y, h, ll);
        hi[(size_t)row*FF + t] = h;
        lo[(size_t)row*FF + t] = ll;
    } else {
        H[(size_t)row*FF + t] = y;
    }
}

// ---------------- duration linear head ----------------------------------------
__global__ void dp_linear(const float* __restrict__ H, const float* __restrict__ lw,
                          const float* __restrict__ lb, float* __restrict__ outp) {
    int row = blockIdx.x;
    int t = threadIdx.x;
    float v = H[(size_t)row*FF + t] * lw[t];
    #pragma unroll
    for (int o = 16; o; o >>= 1) v += __shfl_down_sync(0xffffffffu, v, o);
    __shared__ float s[8];
    if ((t & 31) == 0) s[t >> 5] = v;
    __syncthreads();
    if (t == 0) {
        float a = 0.f;
        #pragma unroll
        for (int i = 0; i < 8; i++) a += s[i];
        outp[row] = a + lb[0];
    }
}

// ---------------- pitch head: dot + mask + bucketize + emb add + split -------
__global__ void pitch_kernel(const float* __restrict__ H, const float* __restrict__ lw,
                             const float* __restrict__ lb, const float* __restrict__ bins,
                             const float* __restrict__ emb, const int* __restrict__ mellen,
                             float* __restrict__ pout) {
    int row = blockIdx.x;
    int b = row >> 11;
    int m = row & (MAXMEL - 1);
    int t = threadIdx.x;
    float v = H[(size_t)row*FF + t] * lw[t];
    #pragma unroll
    for (int o = 16; o; o >>= 1) v += __shfl_down_sync(0xffffffffu, v, o);
    __shared__ float s[8];
    __shared__ int bkt;
    if ((t & 31) == 0) s[t >> 5] = v;
    __syncthreads();
    if (t == 0) {
        float a = 0.f;
        #pragma unroll
        for (int i = 0; i < 8; i++) a += s[i];
        a += lb[0];
        if (m >= mellen[b]) a = 0.f;       // mask BEFORE bucketize (matches ref)
        pout[row] = a;
        int lo = 0, hi = NBINS - 1;
        while (lo < hi) { int mid = (lo + hi) >> 1; if (bins[mid] < a) lo = mid + 1; else hi = mid; }
        bkt = lo;
    }
    __syncthreads();
    float xv = g_bufX[(size_t)row*DD + t] + emb[(size_t)bkt*DD + t];
    bf16 h, l; split1(xv, h, l);
    g_xh[(size_t)row*DD + t] = h;
    g_xl[(size_t)row*DD + t] = l;
}

// ------------------------------- launch ----------------------------------------
extern "C" void kernel_launch(void* const* d_in, const int* in_sizes, int n_in,
                              void* d_out, int out_size) {
    const float* ling   = (const float*)d_in[0];
    const int*   dur    = (const int*)  d_in[1];
    const float* dp_w1  = (const float*)d_in[3];
    const float* dp_b1  = (const float*)d_in[4];
    const float* dp_g1  = (const float*)d_in[5];
    const float* dp_be1 = (const float*)d_in[6];
    const float* dp_w2  = (const float*)d_in[7];
    const float* dp_b2  = (const float*)d_in[8];
    const float* dp_g2  = (const float*)d_in[9];
    const float* dp_be2 = (const float*)d_in[10];
    const float* dp_lw  = (const float*)d_in[11];
    const float* dp_lb  = (const float*)d_in[12];
    const float* pp_w1  = (const float*)d_in[13];
    const float* pp_b1  = (const float*)d_in[14];
    const float* pp_g1  = (const float*)d_in[15];
    const float* pp_be1 = (const float*)d_in[16];
    const float* pp_w2  = (const float*)d_in[17];
    const float* pp_b2  = (const float*)d_in[18];
    const float* pp_g2  = (const float*)d_in[19];
    const float* pp_be2 = (const float*)d_in[20];
    const float* pp_lw  = (const float*)d_in[21];
    const float* pp_lb  = (const float*)d_in[22];
    const float* bins   = (const float*)d_in[23];
    const float* emb    = (const float*)d_in[24];
    const float* proj_w = (const float*)d_in[25];
    const float* proj_b = (const float*)d_in[26];

    float* out = (float*)d_out;

    float *bufA, *bufB;
    bf16 *wh, *wl, *xh, *xl;
    int *idxb, *mellen;
    cudaGetSymbolAddress((void**)&bufA,   g_bufA);
    cudaGetSymbolAddress((void**)&bufB,   g_bufB);
    cudaGetSymbolAddress((void**)&wh,     g_wh);
    cudaGetSymbolAddress((void**)&wl,     g_wl);
    cudaGetSymbolAddress((void**)&xh,     g_xh);
    cudaGetSymbolAddress((void**)&xl,     g_xl);
    cudaGetSymbolAddress((void**)&idxb,   g_idx);
    cudaGetSymbolAddress((void**)&mellen, g_mellen);

    cudaFuncSetAttribute(gemm_mma<3,true,false,8>,  cudaFuncAttributeMaxDynamicSharedMemorySize, SM_TOTAL);
    cudaFuncSetAttribute(gemm_mma<3,true,false,11>, cudaFuncAttributeMaxDynamicSharedMemorySize, SM_TOTAL);
    cudaFuncSetAttribute(gemm_mma<1,false,true,11>, cudaFuncAttributeMaxDynamicSharedMemorySize, SM_TOTAL);

    // 1) weight prep
    prep_w_conv_bf<<<768, 256>>>(dp_w1, wh + 0*WCONV, wl + 0*WCONV);
    prep_w_conv_bf<<<768, 256>>>(dp_w2, wh + 1*WCONV, wl + 1*WCONV);
    prep_w_conv_bf<<<768, 256>>>(pp_w1, wh + 2*WCONV, wl + 2*WCONV);
    prep_w_conv_bf<<<768, 256>>>(pp_w2, wh + 3*WCONV, wl + 3*WCONV);
    prep_w_proj_bf<<<512, 256>>>(proj_w, wh + 4*WCONV, wl + 4*WCONV);

    // 2) length regulator
    length_reg<<<BB, TSLEN>>>(dur, idxb, mellen, out + MEL_OFF);

    // 3) duration predictor (rows = 8192, Tb = 256)
    {
        split_f32<<<(BB*TSLEN*DD/4)/256, 256>>>(ling, xh, xl);
        dim3 g(8192/128, 2);
        gemm_mma<3,true,false,8><<<g, 256, SM_TOTAL>>>(xh, xl, wh + 0*WCONV, wl + 0*WCONV,
            dp_b1, bufA, 256, nullptr);
        layernorm_k<true><<<BB*TSLEN, 256>>>(bufA, dp_g1, dp_be1, xh, xl);
        gemm_mma<3,true,false,8><<<g, 256, SM_TOTAL>>>(xh, xl, wh + 1*WCONV, wl + 1*WCONV,
            dp_b2, bufB, 256, nullptr);
        layernorm_k<false><<<BB*TSLEN, 256>>>(bufB, dp_g2, dp_be2, nullptr, nullptr);
        dp_linear<<<BB*TSLEN, 256>>>(bufB, dp_lw, dp_lb, out + LOGDUR_OFF);
    }

    // 4) pitch predictor (rows = 65536, Tb = 2048)
    {
        gather_x<<<BB*MAXMEL, 64>>>(ling, idxb, mellen);
        dim3 g(65536/128, 2);
        gemm_mma<3,true,false,11><<<g, 256, SM_TOTAL>>>(xh, xl, wh + 2*WCONV, wl + 2*WCONV,
            pp_b1, bufA, 256, nullptr);
        layernorm_k<true><<<BB*MAXMEL, 256>>>(bufA, pp_g1, pp_be1, xh, xl);
        gemm_mma<3,true,false,11><<<g, 256, SM_TOTAL>>>(xh, xl, wh + 3*WCONV, wl + 3*WCONV,
            pp_b2, bufB, 256, nullptr);
        layernorm_k<false><<<BB*MAXMEL, 256>>>(bufB, pp_g2, pp_be2, nullptr, nullptr);
        pitch_kernel<<<BB*MAXMEL, 256>>>(bufB, pp_lw, pp_lb, bins, emb, mellen, out + PITCH_OFF);
    }

    // 5) final projection D -> 2D, masked, into d_out
    {
        dim3 g(65536/128, 4);
        gemm_mma<1,false,true,11><<<g, 256, SM_TOTAL>>>(xh, xl, wh + 4*WCONV, wl + 4*WCONV,
            proj_b, out, 512, mellen);
    }
}